// round 3
// baseline (speedup 1.0000x reference)
#include <cuda_runtime.h>

// Problem constants
#define KCL     1024      // num prototypes
#define DIM     128       // dim
#define BROWS   262144    // batch
#define D2      64        // DIM/2 (float2-packed)
#define TILE_R  128       // rows per block
#define TILE_C  128       // clusters per chunk
#define NCHUNK  (KCL / TILE_C)
#define LDSROW  65        // float2 row stride in smem (odd => conflict-free B reads)

typedef unsigned long long ull;

// Scratch (allocation-free: device globals)
__device__ __align__(256) float g_proto_n[KCL * DIM];
__device__ __align__(256) float g_sums[KCL * DIM];
__device__ float g_counts[KCL];

__device__ __forceinline__ void ffma2(ull &d, ull a, ull b) {
    // packed fp32x2 FMA: 2x fp32 FFMA throughput on Blackwell (ptxas never
    // auto-emits this form; must come from PTX)
    asm("fma.rn.f32x2 %0, %1, %2, %0;" : "+l"(d) : "l"(a), "l"(b));
}
__device__ __forceinline__ float2 unpack2(ull v) {
    float2 f;
    asm("mov.b64 {%0, %1}, %2;" : "=f"(f.x), "=f"(f.y) : "l"(v));
    return f;
}

// ---------------------------------------------------------------------------
__global__ void zero_kernel() {
    int i = blockIdx.x * blockDim.x + threadIdx.x;
    if (i < KCL * DIM) g_sums[i] = 0.0f;
    if (i < KCL)       g_counts[i] = 0.0f;
}

// ---------------------------------------------------------------------------
// L2-normalize prototypes (matches torch F.normalize: x / max(||x||, eps)).
// Embeddings need no normalization: argmax over k of <e/||e||, p_k> equals
// argmax of <e, p_k> (row scale is positive and k-independent).
__global__ void norm_proto_kernel(const float* __restrict__ proto) {
    int k = blockIdx.x;      // one block per prototype row
    int t = threadIdx.x;     // DIM threads
    float v = proto[k * DIM + t];
    float s = v * v;
    #pragma unroll
    for (int m = 16; m; m >>= 1) s += __shfl_xor_sync(0xffffffffu, s, m);
    __shared__ float ws[4];
    if ((t & 31) == 0) ws[t >> 5] = s;
    __syncthreads();
    float tot = ws[0] + ws[1] + ws[2] + ws[3];
    float inv = 1.0f / fmaxf(sqrtf(tot), 1e-12f);
    g_proto_n[k * DIM + t] = v * inv;
}

// ---------------------------------------------------------------------------
// Fused: per-row argmax over all K prototypes (fp32 f32x2 register-tiled GEMM)
// + scatter of raw embeddings into per-cluster sums/counts via REDG atomics.
// Embeddings are read from HBM exactly once (reused from smem for scatter).
__global__ void __launch_bounds__(256, 1)
assign_scatter_kernel(const float* __restrict__ emb) {
    extern __shared__ char smem[];
    float2* embS   = (float2*)smem;                   // [TILE_R][LDSROW]
    float2* protoS = embS + TILE_R * LDSROW;          // [TILE_C][LDSROW]
    int*    rowBest = (int*)(protoS + TILE_C * LDSROW);

    const int tid = threadIdx.x;
    const int tx = tid & 15;          // cluster-group lane (16)
    const int ty = tid >> 4;          // row-group (16)
    const int rowBase = blockIdx.x * TILE_R;

    // ---- load embedding tile (coalesced float4, store as float2 pairs) ----
    {
        const float4* e4 = (const float4*)(emb + (size_t)rowBase * DIM);
        const int wr = tid >> 5;      // 0..7
        const int d4 = tid & 31;      // 0..31
        #pragma unroll
        for (int it = 0; it < 16; ++it) {
            int r = it * 8 + wr;
            float4 v = e4[r * 32 + d4];
            embS[r * LDSROW + 2 * d4]     = make_float2(v.x, v.y);
            embS[r * LDSROW + 2 * d4 + 1] = make_float2(v.z, v.w);
        }
    }

    float bestV[8];
    int   bestI[8];
    #pragma unroll
    for (int i = 0; i < 8; ++i) { bestV[i] = -3.4e38f; bestI[i] = 0; }

    for (int cc = 0; cc < NCHUNK; ++cc) {
        __syncthreads();   // protect protoS reuse (and embS stores on iter 0)
        // ---- load prototype chunk [TILE_C][DIM] from L2-resident g_proto_n ----
        {
            const float4* p4 = (const float4*)(g_proto_n + (size_t)cc * TILE_C * DIM);
            const int wr = tid >> 5;
            const int d4 = tid & 31;
            #pragma unroll
            for (int it = 0; it < 16; ++it) {
                int c = it * 8 + wr;
                float4 v = p4[c * 32 + d4];
                protoS[c * LDSROW + 2 * d4]     = make_float2(v.x, v.y);
                protoS[c * LDSROW + 2 * d4 + 1] = make_float2(v.z, v.w);
            }
        }
        __syncthreads();

        ull acc[8][8];
        #pragma unroll
        for (int i = 0; i < 8; ++i)
            #pragma unroll
            for (int j = 0; j < 8; ++j) acc[i][j] = 0ull;

        const ull* eu = (const ull*)embS;
        const ull* pu = (const ull*)protoS;

        #pragma unroll 2
        for (int k2 = 0; k2 < D2; ++k2) {
            ull a[8], b[8];
            #pragma unroll
            for (int i = 0; i < 8; ++i) a[i] = eu[(ty * 8 + i) * LDSROW + k2];
            #pragma unroll
            for (int j = 0; j < 8; ++j) b[j] = pu[(j * 16 + tx) * LDSROW + k2];
            #pragma unroll
            for (int i = 0; i < 8; ++i)
                #pragma unroll
                for (int j = 0; j < 8; ++j)
                    ffma2(acc[i][j], a[i], b[j]);
        }

        // ---- per-chunk argmax: thread-local over j, then 16-lane butterfly ----
        // Tie-break: lower cluster index wins (matches jnp.argmax first-max).
        #pragma unroll
        for (int i = 0; i < 8; ++i) {
            float v = -3.4e38f; int idx = 0x7fffffff;
            #pragma unroll
            for (int j = 0; j < 8; ++j) {
                float2 f = unpack2(acc[i][j]);
                float s = f.x + f.y;
                int c = cc * TILE_C + j * 16 + tx;
                if (s > v || (s == v && c < idx)) { v = s; idx = c; }
            }
            #pragma unroll
            for (int m = 8; m >= 1; m >>= 1) {
                float ov = __shfl_xor_sync(0xffffffffu, v, m);
                int   oi = __shfl_xor_sync(0xffffffffu, idx, m);
                if (ov > v || (ov == v && oi < idx)) { v = ov; idx = oi; }
            }
            if (v > bestV[i] || (v == bestV[i] && idx < bestI[i])) {
                bestV[i] = v; bestI[i] = idx;
            }
        }
    }

    if (tx == 0) {
        #pragma unroll
        for (int i = 0; i < 8; ++i) rowBest[ty * 8 + i] = bestI[i];
    }
    __syncthreads();

    // ---- scatter: counts + sums via atomics, reading embS (no HBM re-read).
    // d is warp-uniform; lanes sweep 32 consecutive rows -> 32 spread cluster
    // addresses per REDG, low per-address contention.
    if (tid < TILE_R) atomicAdd(&g_counts[rowBest[tid]], 1.0f);

    #pragma unroll 4
    for (int it = 0; it < (TILE_R * DIM) / 256; ++it) {
        int idx = it * 256 + tid;
        int d = idx >> 7;       // 0..127 (fixed per warp)
        int r = idx & 127;      // lanes sweep rows
        float2 f = embS[r * LDSROW + (d >> 1)];
        float v = (d & 1) ? f.y : f.x;
        atomicAdd(&g_sums[rowBest[r] * DIM + d], v);
    }
}

// ---------------------------------------------------------------------------
__global__ void finalize_kernel(const float* __restrict__ proto,
                                float* __restrict__ out) {
    int i = blockIdx.x * blockDim.x + threadIdx.x;  // over K*D
    int k = i >> 7;
    float c = g_counts[k];
    float p = proto[i];
    float m = g_sums[i] / fmaxf(c, 1.0f);
    out[i] = (c > 0.0f) ? (0.9f * p + 0.1f * m) : p;
}

// ---------------------------------------------------------------------------
extern "C" void kernel_launch(void* const* d_in, const int* in_sizes, int n_in,
                              void* d_out, int out_size) {
    const float* emb   = (const float*)d_in[0];   // (B, D) fp32
    const float* proto = (const float*)d_in[1];   // (K, D) fp32
    float* out = (float*)d_out;                   // (K, D) fp32

    const int smemBytes = (TILE_R + TILE_C) * LDSROW * (int)sizeof(float2)
                        + TILE_R * (int)sizeof(int);
    cudaFuncSetAttribute(assign_scatter_kernel,
                         cudaFuncAttributeMaxDynamicSharedMemorySize, smemBytes);

    zero_kernel<<<(KCL * DIM + 255) / 256, 256>>>();
    norm_proto_kernel<<<KCL, DIM>>>(proto);
    assign_scatter_kernel<<<BROWS / TILE_R, 256, smemBytes>>>(emb);
    finalize_kernel<<<(KCL * DIM) / 256, 256>>>(proto, out);
}

// round 6
// speedup vs baseline: 3.5643x; 3.5643x over previous
#include <cuda_runtime.h>
#include <cuda_fp16.h>
#include <cstdint>

// ---------------- problem constants ----------------
#define KCL      1024
#define DIM      128
#define BROWS    262144
#define M_CTA    256              // rows per CTA
#define NCHUNK_P 128              // protos per chunk
#define NCHUNKS  8                // 1024/128
#define BROW_B   272              // padded bytes per proto row (136 halfs) -> LDSM conflict-free
#define HI_BLK   (NCHUNK_P * BROW_B)        // 34816
#define CHUNK_B  (2 * HI_BLK)               // 69632 (hi block + lo block)
#define SMEM_BUFS (2 * CHUNK_B)             // 139264
#define SMEM_TOTAL (SMEM_BUFS + 1024)       // + rowBest[256]

typedef uint32_t u32;
typedef uint64_t u64;

// ---------------- device scratch (no allocs) ----------------
__device__ __align__(16) char g_Bimg[NCHUNKS * CHUNK_B];   // padded hi/lo fp16 proto image
__device__ __align__(16) float g_sums[KCL * DIM];
__device__ float g_counts[KCL];

// ---------------- PTX helpers (all plain-sm_100-legal: sm_80/sm_90 ops) ----
__device__ __forceinline__ u32 smem_u32(const void* p) {
    u32 a;
    asm("{ .reg .u64 t; cvta.to.shared.u64 t, %1; cvt.u32.u64 %0, t; }" : "=r"(a) : "l"(p));
    return a;
}
__device__ __forceinline__ void cp16(u32 dst, const void* src) {
    asm volatile("cp.async.cg.shared.global [%0], [%1], 16;" :: "r"(dst), "l"(src) : "memory");
}
__device__ __forceinline__ void cp_commit() { asm volatile("cp.async.commit_group;" ::: "memory"); }
__device__ __forceinline__ void cp_wait0()  { asm volatile("cp.async.wait_group 0;" ::: "memory"); }

__device__ __forceinline__ void ldsm4(u32* r, u32 addr) {
    asm volatile("ldmatrix.sync.aligned.m8n8.x4.shared.b16 {%0,%1,%2,%3}, [%4];"
                 : "=r"(r[0]), "=r"(r[1]), "=r"(r[2]), "=r"(r[3]) : "r"(addr));
}
__device__ __forceinline__ void mma16(float* d, const u32* a, const u32* b) {
    asm volatile(
        "mma.sync.aligned.m16n8k16.row.col.f32.f16.f16.f32 "
        "{%0,%1,%2,%3}, {%4,%5,%6,%7}, {%8,%9}, {%0,%1,%2,%3};"
        : "+f"(d[0]), "+f"(d[1]), "+f"(d[2]), "+f"(d[3])
        : "r"(a[0]), "r"(a[1]), "r"(a[2]), "r"(a[3]), "r"(b[0]), "r"(b[1]));
}
__device__ __forceinline__ void red4(float* gp, float4 v) {
    asm volatile("red.global.add.v4.f32 [%0], {%1,%2,%3,%4};"
                 :: "l"(gp), "f"(v.x), "f"(v.y), "f"(v.z), "f"(v.w) : "memory");
}
// split fp32 pair -> (hi half2, lo half2) packed as u32
__device__ __forceinline__ u32 split2(float2 v, u32& loOut) {
    __half hx = __float2half_rn(v.x), hy = __float2half_rn(v.y);
    __half lx = __float2half_rn(v.x - __half2float(hx));
    __half ly = __float2half_rn(v.y - __half2float(hy));
    __half2 h2 = __halves2half2(hx, hy), l2 = __halves2half2(lx, ly);
    loOut = *(u32*)&l2;
    return *(u32*)&h2;
}

// ---------------------------------------------------------------------------
// Prep: normalize prototypes (F.normalize semantics: x / max(||x||, eps)),
// fp16 hi/lo split, write padded [chunk][hi|lo][n][k] image. Zero sums/counts.
__global__ void prep_kernel(const float* __restrict__ proto) {
    int k = blockIdx.x;          // prototype row
    int t = threadIdx.x;         // dim
    float v = proto[k * DIM + t];
    float s = v * v;
    #pragma unroll
    for (int m = 16; m; m >>= 1) s += __shfl_xor_sync(0xffffffffu, s, m);
    __shared__ float ws[4];
    if ((t & 31) == 0) ws[t >> 5] = s;
    __syncthreads();
    float tot = ws[0] + ws[1] + ws[2] + ws[3];
    float pn = v * (1.0f / fmaxf(sqrtf(tot), 1e-12f));

    __half hi = __float2half_rn(pn);
    __half lo = __float2half_rn(pn - __half2float(hi));

    int chunk = k >> 7;
    int n = k & 127;
    char* dst = g_Bimg + (size_t)chunk * CHUNK_B;
    *(__half*)(dst + n * BROW_B + t * 2)          = hi;
    *(__half*)(dst + HI_BLK + n * BROW_B + t * 2) = lo;

    g_sums[k * DIM + t] = 0.0f;
    if (t == 0) g_counts[k] = 0.0f;
}

// ---------------------------------------------------------------------------
// Main: 256 threads, 8 warps; each warp owns 2 m16 row tiles (rows w*16..+15
// and +128). A hi/lo fragments resident in registers. B chunks (128 protos,
// hi+lo fp16, padded) double-buffered in smem via cp.async; b-frags via
// non-trans ldmatrix.x4 from [n][k] storage. 3-term split MMA
// (Ahi*Bhi + Alo*Bhi + Ahi*Blo), running argmax, quad-shuffle reduce,
// v4 atomic scatter of raw embeddings.
__global__ void __launch_bounds__(256, 1)
assign_scatter_mma(const float* __restrict__ emb) {
    extern __shared__ char dsm[];
    const u32 sbase = smem_u32(dsm);
    int* rowBest = (int*)(dsm + SMEM_BUFS);

    const int tid  = threadIdx.x;
    const int wid  = tid >> 5;
    const int lane = tid & 31;
    const int g    = lane >> 2;
    const int qi   = lane & 3;

    const float* ebase = emb + (size_t)blockIdx.x * M_CTA * DIM;

    // ---- build resident A fragments (hi/lo) ----
    u32 AHI[2][8][4], ALO[2][8][4];
    #pragma unroll
    for (int t2 = 0; t2 < 2; ++t2) {
        const int rA = t2 * 128 + wid * 16 + g;
        #pragma unroll
        for (int ks = 0; ks < 8; ++ks) {
            const int c0 = ks * 16 + 2 * qi;
            float2 v0 = *(const float2*)(ebase + (size_t)rA * DIM + c0);
            float2 v1 = *(const float2*)(ebase + (size_t)(rA + 8) * DIM + c0);
            float2 v2 = *(const float2*)(ebase + (size_t)rA * DIM + c0 + 8);
            float2 v3 = *(const float2*)(ebase + (size_t)(rA + 8) * DIM + c0 + 8);
            AHI[t2][ks][0] = split2(v0, ALO[t2][ks][0]);
            AHI[t2][ks][1] = split2(v1, ALO[t2][ks][1]);
            AHI[t2][ks][2] = split2(v2, ALO[t2][ks][2]);
            AHI[t2][ks][3] = split2(v3, ALO[t2][ks][3]);
        }
    }

    // per-lane LDSM address offset within a chunk buffer
    const u32 laneOff = (u32)((lane & 7) * BROW_B + (lane >> 3) * 16);
    const u32 bufA[2] = { sbase, sbase + CHUNK_B };

    // ---- prologue: stage chunk 0 ----
    {
        const char* src = g_Bimg;
        #pragma unroll
        for (int j = 0; j < 17; ++j) {
            int off = (j * 256 + tid) * 16;
            cp16(bufA[0] + off, src + off);
        }
        cp_commit(); cp_wait0();
    }
    __syncthreads();

    float bestV[4];
    int   bestI[4];
    #pragma unroll
    for (int q = 0; q < 4; ++q) { bestV[q] = -3.4e38f; bestI[q] = 0; }

    for (int c = 0; c < NCHUNKS; ++c) {
        const int cur = c & 1;
        if (c < NCHUNKS - 1) {
            const char* src = g_Bimg + (size_t)(c + 1) * CHUNK_B;
            #pragma unroll
            for (int j = 0; j < 17; ++j) {
                int off = (j * 256 + tid) * 16;
                cp16(bufA[1 - cur] + off, src + off);
            }
            cp_commit();
        }

        const u32 bb = bufA[cur];
        #pragma unroll 1
        for (int nt = 0; nt < 16; ++nt) {
            float d0[4] = {0.f, 0.f, 0.f, 0.f};
            float d1[4] = {0.f, 0.f, 0.f, 0.f};
            u32 B[16];
            const u32 ntOff = bb + (u32)nt * (8 * BROW_B) + laneOff;
            // hi-B pass: Ahi*Bhi + Alo*Bhi
            #pragma unroll
            for (int gq = 0; gq < 4; ++gq) ldsm4(&B[gq * 4], ntOff + gq * 64);
            #pragma unroll
            for (int ks = 0; ks < 8; ++ks) {
                mma16(d0, AHI[0][ks], &B[2 * ks]);
                mma16(d1, AHI[1][ks], &B[2 * ks]);
                mma16(d0, ALO[0][ks], &B[2 * ks]);
                mma16(d1, ALO[1][ks], &B[2 * ks]);
            }
            // lo-B pass: Ahi*Blo
            #pragma unroll
            for (int gq = 0; gq < 4; ++gq) ldsm4(&B[gq * 4], ntOff + HI_BLK + gq * 64);
            #pragma unroll
            for (int ks = 0; ks < 8; ++ks) {
                mma16(d0, AHI[0][ks], &B[2 * ks]);
                mma16(d1, AHI[1][ks], &B[2 * ks]);
            }
            // fold into running argmax (ascending n + strict '>' => first-max)
            const int c0 = c * NCHUNK_P + nt * 8 + 2 * qi;
            if (d0[0] > bestV[0]) { bestV[0] = d0[0]; bestI[0] = c0; }
            if (d0[1] > bestV[0]) { bestV[0] = d0[1]; bestI[0] = c0 + 1; }
            if (d0[2] > bestV[1]) { bestV[1] = d0[2]; bestI[1] = c0; }
            if (d0[3] > bestV[1]) { bestV[1] = d0[3]; bestI[1] = c0 + 1; }
            if (d1[0] > bestV[2]) { bestV[2] = d1[0]; bestI[2] = c0; }
            if (d1[1] > bestV[2]) { bestV[2] = d1[1]; bestI[2] = c0 + 1; }
            if (d1[2] > bestV[3]) { bestV[3] = d1[2]; bestI[3] = c0; }
            if (d1[3] > bestV[3]) { bestV[3] = d1[3]; bestI[3] = c0 + 1; }
        }

        if (c < NCHUNKS - 1) cp_wait0();
        __syncthreads();
    }

    // ---- quad reduce (lanes 4g..4g+3 hold same rows, different cols) ----
    #pragma unroll
    for (int m = 1; m <= 2; m <<= 1) {
        #pragma unroll
        for (int q = 0; q < 4; ++q) {
            float ov = __shfl_xor_sync(0xffffffffu, bestV[q], m);
            int   oi = __shfl_xor_sync(0xffffffffu, bestI[q], m);
            if (ov > bestV[q] || (ov == bestV[q] && oi < bestI[q])) {
                bestV[q] = ov; bestI[q] = oi;
            }
        }
    }
    if (qi == 0) {
        rowBest[wid * 16 + g]           = bestI[0];
        rowBest[wid * 16 + g + 8]       = bestI[1];
        rowBest[128 + wid * 16 + g]     = bestI[2];
        rowBest[128 + wid * 16 + g + 8] = bestI[3];
    }
    __syncthreads();

    // ---- scatter: counts + v4 reductions of raw embeddings ----
    atomicAdd(&g_counts[rowBest[tid]], 1.0f);

    const float4* e4 = (const float4*)ebase;
    #pragma unroll 4
    for (int it = 0; it < 32; ++it) {
        int idx = it * 256 + tid;
        int r  = idx >> 5;      // 0..255
        int c4 = idx & 31;      // 0..31 float4s per row
        float4 v = e4[r * 32 + c4];
        red4(&g_sums[rowBest[r] * DIM + c4 * 4], v);
    }
}

// ---------------------------------------------------------------------------
__global__ void finalize_kernel(const float* __restrict__ proto,
                                float* __restrict__ out) {
    int i = blockIdx.x * blockDim.x + threadIdx.x;
    int k = i >> 7;
    float c = g_counts[k];
    float p = proto[i];
    float m = g_sums[i] / fmaxf(c, 1.0f);
    out[i] = (c > 0.0f) ? (0.9f * p + 0.1f * m) : p;
}

// ---------------------------------------------------------------------------
extern "C" void kernel_launch(void* const* d_in, const int* in_sizes, int n_in,
                              void* d_out, int out_size) {
    const float* emb   = (const float*)d_in[0];
    const float* proto = (const float*)d_in[1];
    float* out = (float*)d_out;

    cudaFuncSetAttribute(assign_scatter_mma,
                         cudaFuncAttributeMaxDynamicSharedMemorySize, SMEM_TOTAL);

    prep_kernel<<<KCL, DIM>>>(proto);
    assign_scatter_mma<<<BROWS / M_CTA, 256, SMEM_TOTAL>>>(emb);
    finalize_kernel<<<(KCL * DIM) / 256, 256>>>(proto, out);
}

// round 7
// speedup vs baseline: 4.3835x; 1.2298x over previous
#include <cuda_runtime.h>
#include <cuda_fp16.h>
#include <cstdint>

// ---------------- problem constants ----------------
#define KCL      1024
#define DIM      128
#define BROWS    262144
#define M_CTA    256              // rows per CTA (pass 1)
#define NCHUNK_P 128              // protos per chunk
#define NCHUNKS  8                // 1024/128
#define BROW_B   272              // padded bytes per proto row -> LDSM conflict-free
#define HI_BLK   (NCHUNK_P * BROW_B)        // 34816 (hi fp16 block)
#define CHUNK_B  (2 * HI_BLK)               // 69632 (hi + lo blocks)
#define HI_CP    (HI_BLK / 16)              // 2176 cp.async ops per hi chunk
// certified-gap coefficient: 2*delta = 1.97e-3*||e||; 2.5e-3 leaves 27% margin
#define CERT_COEF 2.5e-3f

#define P1_SMEM  (2 * HI_BLK + 1024)            // hi double buffer + rowBest[256]
#define RF_SMEM  (2 * CHUNK_B + 1024)           // full double buffer + rowIdx/rowBest

typedef uint32_t u32;

// ---------------- device scratch (no allocs) ----------------
__device__ __align__(16) char g_Bimg[NCHUNKS * CHUNK_B];   // [chunk][hi|lo] fp16 proto image
__device__ __align__(16) float g_sums[KCL * DIM];
__device__ float g_counts[KCL];
__device__ int   g_list[BROWS];     // flagged row indices
__device__ int   g_nflag;

// ---------------- PTX helpers (plain-sm_100-legal) ----------------
__device__ __forceinline__ u32 smem_u32(const void* p) {
    u32 a;
    asm("{ .reg .u64 t; cvta.to.shared.u64 t, %1; cvt.u32.u64 %0, t; }" : "=r"(a) : "l"(p));
    return a;
}
__device__ __forceinline__ void cp16(u32 dst, const void* src) {
    asm volatile("cp.async.cg.shared.global [%0], [%1], 16;" :: "r"(dst), "l"(src) : "memory");
}
__device__ __forceinline__ void cp_commit() { asm volatile("cp.async.commit_group;" ::: "memory"); }
__device__ __forceinline__ void cp_wait0()  { asm volatile("cp.async.wait_group 0;" ::: "memory"); }

__device__ __forceinline__ void ldsm4(u32* r, u32 addr) {
    asm volatile("ldmatrix.sync.aligned.m8n8.x4.shared.b16 {%0,%1,%2,%3}, [%4];"
                 : "=r"(r[0]), "=r"(r[1]), "=r"(r[2]), "=r"(r[3]) : "r"(addr));
}
__device__ __forceinline__ void mma16(float* d, const u32* a, const u32* b) {
    asm volatile(
        "mma.sync.aligned.m16n8k16.row.col.f32.f16.f16.f32 "
        "{%0,%1,%2,%3}, {%4,%5,%6,%7}, {%8,%9}, {%0,%1,%2,%3};"
        : "+f"(d[0]), "+f"(d[1]), "+f"(d[2]), "+f"(d[3])
        : "r"(a[0]), "r"(a[1]), "r"(a[2]), "r"(a[3]), "r"(b[0]), "r"(b[1]));
}
__device__ __forceinline__ void red4(float* gp, float4 v) {
    asm volatile("red.global.add.v4.f32 [%0], {%1,%2,%3,%4};"
                 :: "l"(gp), "f"(v.x), "f"(v.y), "f"(v.z), "f"(v.w) : "memory");
}
__device__ __forceinline__ u32 split2(float2 v, u32& loOut) {
    __half hx = __float2half_rn(v.x), hy = __float2half_rn(v.y);
    __half lx = __float2half_rn(v.x - __half2float(hx));
    __half ly = __float2half_rn(v.y - __half2float(hy));
    __half2 h2 = __halves2half2(hx, hy), l2 = __halves2half2(lx, ly);
    loOut = *(u32*)&l2;
    return *(u32*)&h2;
}
__device__ __forceinline__ u32 hi2(float2 v) {
    __half2 h2 = __halves2half2(__float2half_rn(v.x), __float2half_rn(v.y));
    return *(u32*)&h2;
}

// ---------------------------------------------------------------------------
// Prep: normalize prototypes (x / max(||x||, eps)), fp16 hi/lo split, write
// padded [chunk][hi|lo][n][k] image. Zero sums/counts/nflag.
__global__ void prep_kernel(const float* __restrict__ proto) {
    int k = blockIdx.x, t = threadIdx.x;
    float v = proto[k * DIM + t];
    float s = v * v;
    #pragma unroll
    for (int m = 16; m; m >>= 1) s += __shfl_xor_sync(0xffffffffu, s, m);
    __shared__ float ws[4];
    if ((t & 31) == 0) ws[t >> 5] = s;
    __syncthreads();
    float pn = v * (1.0f / fmaxf(sqrtf(ws[0] + ws[1] + ws[2] + ws[3]), 1e-12f));

    __half hi = __float2half_rn(pn);
    __half lo = __float2half_rn(pn - __half2float(hi));

    int chunk = k >> 7, n = k & 127;
    char* dst = g_Bimg + (size_t)chunk * CHUNK_B;
    *(__half*)(dst + n * BROW_B + t * 2)          = hi;
    *(__half*)(dst + HI_BLK + n * BROW_B + t * 2) = lo;

    g_sums[k * DIM + t] = 0.0f;
    if (t == 0) g_counts[k] = 0.0f;
    if (k == 0 && t == 0) g_nflag = 0;
}

// ---------------------------------------------------------------------------
// Pass 1: hi-only fp16 GEMM, per-row top-2, certified assignment + scatter for
// rows with gap > CERT_COEF*||e||; others appended to g_list for refinement.
__global__ void __launch_bounds__(256, 2)
pass1_kernel(const float* __restrict__ emb) {
    extern __shared__ char dsm[];
    const u32 sbase = smem_u32(dsm);
    int* rowBest = (int*)(dsm + 2 * HI_BLK);

    const int tid  = threadIdx.x;
    const int wid  = tid >> 5;
    const int lane = tid & 31;
    const int g    = lane >> 2;
    const int qi   = lane & 3;
    const int rowBase = blockIdx.x * M_CTA;
    const float* ebase = emb + (size_t)rowBase * DIM;

    // ---- A hi fragments + row norms ----
    u32 AHI[2][8][4];
    float nrm2[4] = {0.f, 0.f, 0.f, 0.f};
    #pragma unroll
    for (int t2 = 0; t2 < 2; ++t2) {
        const int rA = t2 * 128 + wid * 16 + g;
        #pragma unroll
        for (int ks = 0; ks < 8; ++ks) {
            const int c0 = ks * 16 + 2 * qi;
            float2 v0 = *(const float2*)(ebase + (size_t)rA * DIM + c0);
            float2 v1 = *(const float2*)(ebase + (size_t)(rA + 8) * DIM + c0);
            float2 v2 = *(const float2*)(ebase + (size_t)rA * DIM + c0 + 8);
            float2 v3 = *(const float2*)(ebase + (size_t)(rA + 8) * DIM + c0 + 8);
            AHI[t2][ks][0] = hi2(v0); AHI[t2][ks][1] = hi2(v1);
            AHI[t2][ks][2] = hi2(v2); AHI[t2][ks][3] = hi2(v3);
            nrm2[t2 * 2]     += v0.x * v0.x + v0.y * v0.y + v2.x * v2.x + v2.y * v2.y;
            nrm2[t2 * 2 + 1] += v1.x * v1.x + v1.y * v1.y + v3.x * v3.x + v3.y * v3.y;
        }
    }
    #pragma unroll
    for (int m = 1; m <= 2; m <<= 1)
        #pragma unroll
        for (int q = 0; q < 4; ++q)
            nrm2[q] += __shfl_xor_sync(0xffffffffu, nrm2[q], m);

    const u32 laneOff = (u32)((lane & 7) * BROW_B + (lane >> 3) * 16);
    const u32 bufA[2] = { sbase, sbase + HI_BLK };

    // stage hi-chunk 0
    #pragma unroll
    for (int j = 0; j < 9; ++j) {
        int idx = j * 256 + tid;
        if (idx < HI_CP) cp16(bufA[0] + idx * 16, g_Bimg + idx * 16);
    }
    cp_commit(); cp_wait0();
    __syncthreads();

    float v1a[4], v2a[4]; int i1a[4];
    #pragma unroll
    for (int q = 0; q < 4; ++q) { v1a[q] = -3.4e38f; v2a[q] = -3.4e38f; i1a[q] = 0; }

    for (int c = 0; c < NCHUNKS; ++c) {
        const int cur = c & 1;
        if (c < NCHUNKS - 1) {
            const char* src = g_Bimg + (size_t)(c + 1) * CHUNK_B;
            #pragma unroll
            for (int j = 0; j < 9; ++j) {
                int idx = j * 256 + tid;
                if (idx < HI_CP) cp16(bufA[1 - cur] + idx * 16, src + idx * 16);
            }
            cp_commit();
        }

        const u32 bb = bufA[cur];
        #pragma unroll 1
        for (int nt = 0; nt < 16; ++nt) {
            float d0[4] = {0.f, 0.f, 0.f, 0.f};
            float d1[4] = {0.f, 0.f, 0.f, 0.f};
            u32 B[16];
            const u32 ntOff = bb + (u32)nt * (8 * BROW_B) + laneOff;
            #pragma unroll
            for (int gq = 0; gq < 4; ++gq) ldsm4(&B[gq * 4], ntOff + gq * 64);
            #pragma unroll
            for (int ks = 0; ks < 8; ++ks) {
                mma16(d0, AHI[0][ks], &B[2 * ks]);
                mma16(d1, AHI[1][ks], &B[2 * ks]);
            }
            const int c0 = c * NCHUNK_P + nt * 8 + 2 * qi;
            #pragma unroll
            for (int q = 0; q < 4; ++q) {
                const float da = (q < 2) ? d0[q * 2] : d1[(q - 2) * 2];
                const float db = (q < 2) ? d0[q * 2 + 1] : d1[(q - 2) * 2 + 1];
                // careful slot map: q0=t0/g, q1=t0/g+8, q2=t1/g, q3=t1/g+8
                if (da > v1a[q]) { v2a[q] = v1a[q]; v1a[q] = da; i1a[q] = c0; }
                else if (da > v2a[q]) v2a[q] = da;
                if (db > v1a[q]) { v2a[q] = v1a[q]; v1a[q] = db; i1a[q] = c0 + 1; }
                else if (db > v2a[q]) v2a[q] = db;
            }
        }
        if (c < NCHUNKS - 1) cp_wait0();
        __syncthreads();
    }

    // quad reduce top-2 (lanes of a quad hold disjoint cluster columns)
    #pragma unroll
    for (int m = 1; m <= 2; m <<= 1) {
        #pragma unroll
        for (int q = 0; q < 4; ++q) {
            float ov1 = __shfl_xor_sync(0xffffffffu, v1a[q], m);
            int   oi1 = __shfl_xor_sync(0xffffffffu, i1a[q], m);
            float ov2 = __shfl_xor_sync(0xffffffffu, v2a[q], m);
            if (ov1 > v1a[q]) {
                v2a[q] = fmaxf(v1a[q], ov2); v1a[q] = ov1; i1a[q] = oi1;
            } else if (ov1 == v1a[q]) {
                v2a[q] = v1a[q];                     // exact tie -> force flag
                i1a[q] = min(i1a[q], oi1);
            } else {
                v2a[q] = fmaxf(v2a[q], ov1);
            }
        }
    }

    if (qi == 0) {
        #pragma unroll
        for (int q = 0; q < 4; ++q) {
            const int rl = (q >> 1) * 128 + wid * 16 + (q & 1) * 8 + g;
            const float delta = CERT_COEF * sqrtf(nrm2[q]);
            if (v1a[q] - v2a[q] > delta) {
                rowBest[rl] = i1a[q];
            } else {
                rowBest[rl] = -1;
                int pos = atomicAdd(&g_nflag, 1);
                g_list[pos] = rowBase + rl;
            }
        }
    }
    __syncthreads();

    // ---- scatter certified rows ----
    {
        int rb = rowBest[tid];
        if (rb >= 0) atomicAdd(&g_counts[rb], 1.0f);
    }
    const float4* e4 = (const float4*)ebase;
    #pragma unroll 4
    for (int it = 0; it < 32; ++it) {
        int idx = it * 256 + tid;
        int r  = idx >> 5;
        int c4 = idx & 31;
        int rb = rowBest[r];
        if (rb >= 0) red4(&g_sums[rb * DIM + c4 * 4], e4[r * 32 + c4]);
    }
}

// ---------------------------------------------------------------------------
// Refine: persistent kernel over flagged rows; 128-row gathered tiles, full
// 3-term fp16 split (Ahi*Bhi + Alo*Bhi + Ahi*Blo), argmax (first-max), scatter.
__global__ void __launch_bounds__(256, 1)
refine_kernel(const float* __restrict__ emb) {
    extern __shared__ char dsm[];
    const u32 sbase = smem_u32(dsm);
    int* rowIdx  = (int*)(dsm + 2 * CHUNK_B);
    int* rbBest  = rowIdx + 128;

    const int tid  = threadIdx.x;
    const int wid  = tid >> 5;
    const int lane = tid & 31;
    const int g    = lane >> 2;
    const int qi   = lane & 3;

    const int nf = *(volatile int*)&g_nflag;
    const int nTiles = (nf + 127) >> 7;
    const u32 laneOff = (u32)((lane & 7) * BROW_B + (lane >> 3) * 16);
    const u32 bufA[2] = { sbase, sbase + CHUNK_B };

    for (int t = blockIdx.x; t < nTiles; t += gridDim.x) {
        if (tid < 128) {
            int srci = t * 128 + tid;
            rowIdx[tid] = (srci < nf) ? g_list[srci] : -1;
        }
        __syncthreads();

        const int r0 = rowIdx[wid * 16 + g];
        const int r1 = rowIdx[wid * 16 + g + 8];
        const float* e0 = emb + (size_t)max(r0, 0) * DIM;
        const float* e1 = emb + (size_t)max(r1, 0) * DIM;

        u32 AHI[8][4], ALO[8][4];
        #pragma unroll
        for (int ks = 0; ks < 8; ++ks) {
            const int c0 = ks * 16 + 2 * qi;
            float2 v0 = *(const float2*)(e0 + c0);
            float2 v1 = *(const float2*)(e1 + c0);
            float2 v2 = *(const float2*)(e0 + c0 + 8);
            float2 v3 = *(const float2*)(e1 + c0 + 8);
            AHI[ks][0] = split2(v0, ALO[ks][0]);
            AHI[ks][1] = split2(v1, ALO[ks][1]);
            AHI[ks][2] = split2(v2, ALO[ks][2]);
            AHI[ks][3] = split2(v3, ALO[ks][3]);
        }

        // stage full chunk 0 (hi+lo)
        #pragma unroll
        for (int j = 0; j < 17; ++j) {
            int off = (j * 256 + tid) * 16;
            cp16(bufA[0] + off, g_Bimg + off);
        }
        cp_commit(); cp_wait0();
        __syncthreads();

        float bV0 = -3.4e38f, bV1 = -3.4e38f;
        int   bI0 = 0, bI1 = 0;

        for (int c = 0; c < NCHUNKS; ++c) {
            const int cur = c & 1;
            if (c < NCHUNKS - 1) {
                const char* src = g_Bimg + (size_t)(c + 1) * CHUNK_B;
                #pragma unroll
                for (int j = 0; j < 17; ++j) {
                    int off = (j * 256 + tid) * 16;
                    cp16(bufA[1 - cur] + off, src + off);
                }
                cp_commit();
            }
            const u32 bb = bufA[cur];
            #pragma unroll 1
            for (int nt = 0; nt < 16; ++nt) {
                float d[4] = {0.f, 0.f, 0.f, 0.f};
                u32 B[16];
                const u32 ntOff = bb + (u32)nt * (8 * BROW_B) + laneOff;
                #pragma unroll
                for (int gq = 0; gq < 4; ++gq) ldsm4(&B[gq * 4], ntOff + gq * 64);
                #pragma unroll
                for (int ks = 0; ks < 8; ++ks) {
                    mma16(d, AHI[ks], &B[2 * ks]);
                    mma16(d, ALO[ks], &B[2 * ks]);
                }
                #pragma unroll
                for (int gq = 0; gq < 4; ++gq) ldsm4(&B[gq * 4], ntOff + HI_BLK + gq * 64);
                #pragma unroll
                for (int ks = 0; ks < 8; ++ks)
                    mma16(d, AHI[ks], &B[2 * ks]);

                const int c0 = c * NCHUNK_P + nt * 8 + 2 * qi;
                if (d[0] > bV0) { bV0 = d[0]; bI0 = c0; }
                if (d[1] > bV0) { bV0 = d[1]; bI0 = c0 + 1; }
                if (d[2] > bV1) { bV1 = d[2]; bI1 = c0; }
                if (d[3] > bV1) { bV1 = d[3]; bI1 = c0 + 1; }
            }
            if (c < NCHUNKS - 1) cp_wait0();
            __syncthreads();
        }

        #pragma unroll
        for (int m = 1; m <= 2; m <<= 1) {
            float ov = __shfl_xor_sync(0xffffffffu, bV0, m);
            int   oi = __shfl_xor_sync(0xffffffffu, bI0, m);
            if (ov > bV0 || (ov == bV0 && oi < bI0)) { bV0 = ov; bI0 = oi; }
            ov = __shfl_xor_sync(0xffffffffu, bV1, m);
            oi = __shfl_xor_sync(0xffffffffu, bI1, m);
            if (ov > bV1 || (ov == bV1 && oi < bI1)) { bV1 = ov; bI1 = oi; }
        }
        if (qi == 0) {
            rbBest[wid * 16 + g]     = bI0;
            rbBest[wid * 16 + g + 8] = bI1;
        }
        __syncthreads();

        // scatter flagged rows
        if (tid < 128 && rowIdx[tid] >= 0)
            atomicAdd(&g_counts[rbBest[tid]], 1.0f);
        #pragma unroll 4
        for (int it = 0; it < 16; ++it) {
            int idx = it * 256 + tid;
            int r  = idx >> 5;
            int c4 = idx & 31;
            int ri = rowIdx[r];
            if (ri >= 0) {
                float4 v = *(const float4*)(emb + (size_t)ri * DIM + c4 * 4);
                red4(&g_sums[rbBest[r] * DIM + c4 * 4], v);
            }
        }
        __syncthreads();
    }
}

// ---------------------------------------------------------------------------
__global__ void finalize_kernel(const float* __restrict__ proto,
                                float* __restrict__ out) {
    int i = blockIdx.x * blockDim.x + threadIdx.x;
    int k = i >> 7;
    float c = g_counts[k];
    float p = proto[i];
    float m = g_sums[i] / fmaxf(c, 1.0f);
    out[i] = (c > 0.0f) ? (0.9f * p + 0.1f * m) : p;
}

// ---------------------------------------------------------------------------
extern "C" void kernel_launch(void* const* d_in, const int* in_sizes, int n_in,
                              void* d_out, int out_size) {
    const float* emb   = (const float*)d_in[0];
    const float* proto = (const float*)d_in[1];
    float* out = (float*)d_out;

    cudaFuncSetAttribute(pass1_kernel,
                         cudaFuncAttributeMaxDynamicSharedMemorySize, P1_SMEM);
    cudaFuncSetAttribute(refine_kernel,
                         cudaFuncAttributeMaxDynamicSharedMemorySize, RF_SMEM);

    prep_kernel<<<KCL, DIM>>>(proto);
    pass1_kernel<<<BROWS / M_CTA, 256, P1_SMEM>>>(emb);
    refine_kernel<<<148, 256, RF_SMEM>>>(emb);
    finalize_kernel<<<(KCL * DIM) / 256, 256>>>(proto, out);
}